// round 1
// baseline (speedup 1.0000x reference)
#include <cuda_runtime.h>

#define S_NODES 100000
#define T_NODES 20000
#define E_EDGES 1000000
#define SRC_DIM 256
#define EMB_DIM 128
#define TGT_DIM 128

// Scratch (allocation-free rule: __device__ globals)
__device__ float g_x[S_NODES * EMB_DIM];    // 51.2 MB  (fits in L2)
__device__ float g_acc[T_NODES * EMB_DIM];  // 10.24 MB
__device__ int   g_cnt[T_NODES];

// ---------------------------------------------------------------------------
// zero accumulators
// ---------------------------------------------------------------------------
__global__ void zero_kernel() {
    int stride = gridDim.x * blockDim.x;
    int n = T_NODES * EMB_DIM;
    for (int i = blockIdx.x * blockDim.x + threadIdx.x; i < n; i += stride)
        g_acc[i] = 0.0f;
    for (int j = blockIdx.x * blockDim.x + threadIdx.x; j < T_NODES; j += stride)
        g_cnt[j] = 0;
}

// ---------------------------------------------------------------------------
// Generic fp32 GEMM, N fixed at 128, with per-output-row scaling epilogue.
// MODE 0: scale = 1 / xnorm[row]          (x = A@B / xnorm)
// MODE 1: scale = 1 / max(cnt[row], 1)    (out = (acc@W) / cnt  == mean @ W)
// BM=128, BN=128, BK=16, 256 threads, 8x8 register tile per thread.
// ---------------------------------------------------------------------------
template <int MODE>
__global__ void __launch_bounds__(256)
gemm128(const float* __restrict__ A, const float* __restrict__ B,
        float* __restrict__ C, int M, int K,
        const float* __restrict__ xnorm, const int* __restrict__ cnt) {
    __shared__ float As[16][128];   // [k][m] 8 KB
    __shared__ float Bs[16][128];   // [k][n] 8 KB

    const int tid = threadIdx.x;        // 0..255
    const int tx  = tid & 15;           // col group (8 cols each)
    const int ty  = tid >> 4;           // row group (8 rows each)
    const int row0 = blockIdx.x * 128;

    float c[8][8];
#pragma unroll
    for (int i = 0; i < 8; i++)
#pragma unroll
        for (int j = 0; j < 8; j++) c[i][j] = 0.0f;

    for (int k0 = 0; k0 < K; k0 += 16) {
        // Load A tile: 128 rows x 16 k  = 512 float4 (2 per thread)
#pragma unroll
        for (int l = 0; l < 2; l++) {
            int idx = tid * 2 + l;          // 0..511
            int r   = idx >> 2;             // 0..127
            int kq  = (idx & 3) * 4;        // 0,4,8,12
            int grow = row0 + r;
            float4 v = make_float4(0.f, 0.f, 0.f, 0.f);
            if (grow < M)
                v = *(const float4*)(A + (size_t)grow * K + k0 + kq);
            As[kq + 0][r] = v.x;
            As[kq + 1][r] = v.y;
            As[kq + 2][r] = v.z;
            As[kq + 3][r] = v.w;
        }
        // Load B tile: 16 rows x 128 cols = 512 float4 (2 per thread)
#pragma unroll
        for (int l = 0; l < 2; l++) {
            int idx = tid * 2 + l;
            int kr  = idx >> 5;             // 0..15
            int nq  = (idx & 31) * 4;       // 0..124
            *(float4*)&Bs[kr][nq] = *(const float4*)(B + (size_t)(k0 + kr) * 128 + nq);
        }
        __syncthreads();

#pragma unroll
        for (int k = 0; k < 16; k++) {
            float a[8], b[8];
#pragma unroll
            for (int i = 0; i < 8; i++) a[i] = As[k][ty * 8 + i];
#pragma unroll
            for (int j = 0; j < 8; j++) b[j] = Bs[k][tx * 8 + j];
#pragma unroll
            for (int i = 0; i < 8; i++)
#pragma unroll
                for (int j = 0; j < 8; j++) c[i][j] += a[i] * b[j];
        }
        __syncthreads();
    }

    // Epilogue: per-row scale, store
#pragma unroll
    for (int i = 0; i < 8; i++) {
        int grow = row0 + ty * 8 + i;
        if (grow >= M) continue;
        float s;
        if (MODE == 0) {
            s = 1.0f / xnorm[grow];
        } else {
            int cc = cnt[grow];
            s = 1.0f / (float)(cc > 1 ? cc : 1);
        }
#pragma unroll
        for (int j = 0; j < 8; j += 4) {
            float4 v;
            v.x = c[i][j + 0] * s;
            v.y = c[i][j + 1] * s;
            v.z = c[i][j + 2] * s;
            v.w = c[i][j + 3] * s;
            *(float4*)(C + (size_t)grow * 128 + tx * 8 + j) = v;
        }
    }
}

// ---------------------------------------------------------------------------
// Warp-per-edge scatter: acc[dst] += x[src]; cnt[dst] += 1
// ---------------------------------------------------------------------------
__global__ void __launch_bounds__(256)
scatter_kernel(const int* __restrict__ src, const int* __restrict__ dst) {
    int warp = (blockIdx.x * blockDim.x + threadIdx.x) >> 5;
    int lane = threadIdx.x & 31;
    if (warp >= E_EDGES) return;
    int s = src[warp];
    int d = dst[warp];
    float4 v = ((const float4*)(g_x + (size_t)s * EMB_DIM))[lane];
    float* a = g_acc + (size_t)d * EMB_DIM + lane * 4;
    atomicAdd(a + 0, v.x);
    atomicAdd(a + 1, v.y);
    atomicAdd(a + 2, v.z);
    atomicAdd(a + 3, v.w);
    if (lane == 0) atomicAdd(&g_cnt[d], 1);
}

// ---------------------------------------------------------------------------
// launch
// ---------------------------------------------------------------------------
extern "C" void kernel_launch(void* const* d_in, const int* in_sizes, int n_in,
                              void* d_out, int out_size) {
    const float* source_feat = (const float*)d_in[0];  // [N, 256]
    const int*   src_idx     = (const int*)d_in[1];    // [E]
    const int*   dst_idx     = (const int*)d_in[2];    // [E]
    // d_in[3] = range_list (unused)
    const float* x_norm      = (const float*)d_in[4];  // [N]
    const float* embed       = (const float*)d_in[5];  // [256, 128]
    const float* weight      = (const float*)d_in[6];  // [128, 128]
    float* out = (float*)d_out;                        // [T, 128]

    float* gx;
    float* gacc;
    int*   gcnt;
    cudaGetSymbolAddress((void**)&gx,   g_x);
    cudaGetSymbolAddress((void**)&gacc, g_acc);
    cudaGetSymbolAddress((void**)&gcnt, g_cnt);

    // 1. zero accumulators
    zero_kernel<<<1024, 256>>>();

    // 2. x = (source_feat[:S] @ embed) / x_norm[:S]      -> g_x [S, 128]
    gemm128<0><<<(S_NODES + 127) / 128, 256>>>(source_feat, embed, gx,
                                               S_NODES, SRC_DIM, x_norm, nullptr);

    // 3. scatter-sum + counts (warp per edge)
    {
        int warps_per_block = 256 / 32;
        int blocks = (E_EDGES + warps_per_block - 1) / warps_per_block;
        scatter_kernel<<<blocks, 256>>>(src_idx, dst_idx);
    }

    // 4. out = (acc / max(cnt,1)) @ weight               -> d_out [T, 128]
    gemm128<1><<<(T_NODES + 127) / 128, 256>>>(gacc, weight, out,
                                               T_NODES, EMB_DIM, nullptr, gcnt);
}

// round 2
// speedup vs baseline: 1.0361x; 1.0361x over previous
#include <cuda_runtime.h>

#define S_NODES 100000
#define T_NODES 20000
#define E_EDGES 1000000
#define SRC_DIM 256
#define EMB_DIM 128
#define TGT_DIM 128

// Scratch (allocation-free rule: __device__ globals)
__device__ float g_x[S_NODES * EMB_DIM];    // 51.2 MB (L2-resident)
__device__ float g_acc[T_NODES * EMB_DIM];  // 10.24 MB (holds MEAN now)
__device__ int   g_cnt[T_NODES];
__device__ int   g_off[T_NODES];
__device__ int   g_cur[T_NODES];
__device__ int   g_bucket[E_EDGES];

// ---------------------------------------------------------------------------
__global__ void zero_cnt_kernel() {
    int i = blockIdx.x * blockDim.x + threadIdx.x;
    if (i < T_NODES) g_cnt[i] = 0;
}

__global__ void histogram_kernel(const int* __restrict__ dst) {
    int stride = gridDim.x * blockDim.x;
    for (int i = blockIdx.x * blockDim.x + threadIdx.x; i < E_EDGES; i += stride)
        atomicAdd(&g_cnt[dst[i]], 1);
}

// Single-block exclusive scan of g_cnt -> g_off (and g_cur copy).
// 1024 threads, each owns 20 consecutive buckets.
__global__ void __launch_bounds__(1024)
scan_kernel() {
    __shared__ int sums[1024];
    const int tid = threadIdx.x;
    const int PER = 20;  // 1024*20 >= 20000
    int base = tid * PER;

    int local = 0;
#pragma unroll
    for (int j = 0; j < PER; j++) {
        int b = base + j;
        if (b < T_NODES) local += g_cnt[b];
    }
    sums[tid] = local;
    __syncthreads();

    // Hillis-Steele inclusive scan over 1024 thread sums
    for (int d = 1; d < 1024; d <<= 1) {
        int v = sums[tid];
        int add = (tid >= d) ? sums[tid - d] : 0;
        __syncthreads();
        sums[tid] = v + add;
        __syncthreads();
    }

    int run = (tid > 0) ? sums[tid - 1] : 0;  // exclusive prefix for this thread
#pragma unroll
    for (int j = 0; j < PER; j++) {
        int b = base + j;
        if (b < T_NODES) {
            g_off[b] = run;
            g_cur[b] = run;
            run += g_cnt[b];
        }
    }
}

__global__ void fill_kernel(const int* __restrict__ src, const int* __restrict__ dst) {
    int stride = gridDim.x * blockDim.x;
    for (int i = blockIdx.x * blockDim.x + threadIdx.x; i < E_EDGES; i += stride) {
        int d = dst[i];
        int pos = atomicAdd(&g_cur[d], 1);
        g_bucket[pos] = src[i];
    }
}

// ---------------------------------------------------------------------------
// Warp-per-target segmented mean: g_acc[t] = mean over edges of g_x[src]
// lane handles 4 floats (float4). 4-way unrolled independent accumulators.
// ---------------------------------------------------------------------------
__global__ void __launch_bounds__(256)
aggregate_kernel() {
    int warp = (blockIdx.x * blockDim.x + threadIdx.x) >> 5;
    int lane = threadIdx.x & 31;
    if (warp >= T_NODES) return;

    int beg = g_off[warp];
    int n   = g_cnt[warp];
    const float4* xb = (const float4*)g_x;

    float4 a0 = make_float4(0.f, 0.f, 0.f, 0.f);
    float4 a1 = a0, a2 = a0, a3 = a0;

    int i = 0;
    for (; i + 4 <= n; i += 4) {
        int s0 = g_bucket[beg + i + 0];
        int s1 = g_bucket[beg + i + 1];
        int s2 = g_bucket[beg + i + 2];
        int s3 = g_bucket[beg + i + 3];
        float4 v0 = xb[(size_t)s0 * 32 + lane];
        float4 v1 = xb[(size_t)s1 * 32 + lane];
        float4 v2 = xb[(size_t)s2 * 32 + lane];
        float4 v3 = xb[(size_t)s3 * 32 + lane];
        a0.x += v0.x; a0.y += v0.y; a0.z += v0.z; a0.w += v0.w;
        a1.x += v1.x; a1.y += v1.y; a1.z += v1.z; a1.w += v1.w;
        a2.x += v2.x; a2.y += v2.y; a2.z += v2.z; a2.w += v2.w;
        a3.x += v3.x; a3.y += v3.y; a3.z += v3.z; a3.w += v3.w;
    }
    for (; i < n; i++) {
        int s = g_bucket[beg + i];
        float4 v = xb[(size_t)s * 32 + lane];
        a0.x += v.x; a0.y += v.y; a0.z += v.z; a0.w += v.w;
    }

    float inv = 1.0f / (float)(n > 1 ? n : 1);
    float4 r;
    r.x = (a0.x + a1.x + a2.x + a3.x) * inv;
    r.y = (a0.y + a1.y + a2.y + a3.y) * inv;
    r.z = (a0.z + a1.z + a2.z + a3.z) * inv;
    r.w = (a0.w + a1.w + a2.w + a3.w) * inv;
    ((float4*)g_acc)[(size_t)warp * 32 + lane] = r;
}

// ---------------------------------------------------------------------------
// fp32 GEMM, N fixed 128, per-row-scale epilogue.
// MODE 0: scale = 1/xnorm[row];  MODE 2: no scale.
// BM=128, BN=128, BK=16, 256 threads, 8x8 register tile.
// ---------------------------------------------------------------------------
template <int MODE>
__global__ void __launch_bounds__(256)
gemm128(const float* __restrict__ A, const float* __restrict__ B,
        float* __restrict__ C, int M, int K,
        const float* __restrict__ xnorm) {
    __shared__ float As[16][128];
    __shared__ float Bs[16][128];

    const int tid = threadIdx.x;
    const int tx  = tid & 15;
    const int ty  = tid >> 4;
    const int row0 = blockIdx.x * 128;

    float c[8][8];
#pragma unroll
    for (int i = 0; i < 8; i++)
#pragma unroll
        for (int j = 0; j < 8; j++) c[i][j] = 0.0f;

    for (int k0 = 0; k0 < K; k0 += 16) {
#pragma unroll
        for (int l = 0; l < 2; l++) {
            int idx = tid * 2 + l;
            int r   = idx >> 2;
            int kq  = (idx & 3) * 4;
            int grow = row0 + r;
            float4 v = make_float4(0.f, 0.f, 0.f, 0.f);
            if (grow < M)
                v = *(const float4*)(A + (size_t)grow * K + k0 + kq);
            As[kq + 0][r] = v.x;
            As[kq + 1][r] = v.y;
            As[kq + 2][r] = v.z;
            As[kq + 3][r] = v.w;
        }
#pragma unroll
        for (int l = 0; l < 2; l++) {
            int idx = tid * 2 + l;
            int kr  = idx >> 5;
            int nq  = (idx & 31) * 4;
            *(float4*)&Bs[kr][nq] = *(const float4*)(B + (size_t)(k0 + kr) * 128 + nq);
        }
        __syncthreads();

#pragma unroll
        for (int k = 0; k < 16; k++) {
            float a[8], b[8];
#pragma unroll
            for (int i = 0; i < 8; i++) a[i] = As[k][ty * 8 + i];
#pragma unroll
            for (int j = 0; j < 8; j++) b[j] = Bs[k][tx * 8 + j];
#pragma unroll
            for (int i = 0; i < 8; i++)
#pragma unroll
                for (int j = 0; j < 8; j++) c[i][j] += a[i] * b[j];
        }
        __syncthreads();
    }

#pragma unroll
    for (int i = 0; i < 8; i++) {
        int grow = row0 + ty * 8 + i;
        if (grow >= M) continue;
        float s = 1.0f;
        if (MODE == 0) s = 1.0f / xnorm[grow];
#pragma unroll
        for (int j = 0; j < 8; j += 4) {
            float4 v;
            v.x = c[i][j + 0] * s;
            v.y = c[i][j + 1] * s;
            v.z = c[i][j + 2] * s;
            v.w = c[i][j + 3] * s;
            *(float4*)(C + (size_t)grow * 128 + tx * 8 + j) = v;
        }
    }
}

// ---------------------------------------------------------------------------
extern "C" void kernel_launch(void* const* d_in, const int* in_sizes, int n_in,
                              void* d_out, int out_size) {
    const float* source_feat = (const float*)d_in[0];  // [N, 256]
    const int*   src_idx     = (const int*)d_in[1];    // [E]
    const int*   dst_idx     = (const int*)d_in[2];    // [E]
    // d_in[3] = range_list (unused)
    const float* x_norm      = (const float*)d_in[4];  // [N]
    const float* embed       = (const float*)d_in[5];  // [256, 128]
    const float* weight      = (const float*)d_in[6];  // [128, 128]
    float* out = (float*)d_out;                        // [T, 128]

    float* gx;
    float* gacc;
    cudaGetSymbolAddress((void**)&gx,   g_x);
    cudaGetSymbolAddress((void**)&gacc, g_acc);

    // CSR build (int atomics only)
    zero_cnt_kernel<<<(T_NODES + 255) / 256, 256>>>();
    histogram_kernel<<<1024, 256>>>(dst_idx);
    scan_kernel<<<1, 1024>>>();
    fill_kernel<<<1024, 256>>>(src_idx, dst_idx);

    // x = (source_feat[:S] @ embed) / x_norm[:S]
    gemm128<0><<<(S_NODES + 127) / 128, 256>>>(source_feat, embed, gx,
                                               S_NODES, SRC_DIM, x_norm);

    // segmented mean over edges -> g_acc
    aggregate_kernel<<<(T_NODES * 32 + 255) / 256, 256>>>();

    // out = mean @ weight
    gemm128<2><<<(T_NODES + 127) / 128, 256>>>(gacc, weight, out,
                                               T_NODES, EMB_DIM, nullptr);
}

// round 5
// speedup vs baseline: 2.0053x; 1.9353x over previous
#include <cuda_runtime.h>

#define S_NODES 100000
#define T_NODES 20000
#define N_NODES 120000
#define E_EDGES 1000000
#define SRC_DIM 256
#define EMB_DIM 128
#define TGT_DIM 128

// Scratch (__device__ globals; no allocations allowed)
__device__ float g_aggr[T_NODES * SRC_DIM];   // 20.5 MB  mean of scaled 256-dim feats
__device__ float g_M[SRC_DIM * TGT_DIM];      // 128 KB   embed @ weight
__device__ float g_invnorm[S_NODES];
__device__ int   g_cnt[T_NODES];
__device__ int   g_off[T_NODES];
__device__ int   g_cur[T_NODES];
__device__ int   g_bucket[E_EDGES];

// ---------------------------------------------------------------------------
__global__ void prep_kernel(const float* __restrict__ xnorm) {
    int i = blockIdx.x * blockDim.x + threadIdx.x;
    if (i < T_NODES) g_cnt[i] = 0;
    if (i < S_NODES) g_invnorm[i] = 1.0f / xnorm[i];
}

__global__ void histogram_kernel(const int* __restrict__ dst) {
    int stride = gridDim.x * blockDim.x;
    for (int i = blockIdx.x * blockDim.x + threadIdx.x; i < E_EDGES; i += stride)
        atomicAdd(&g_cnt[dst[i]], 1);
}

// Single-block exclusive scan of g_cnt -> g_off, g_cur
__global__ void __launch_bounds__(1024)
scan_kernel() {
    __shared__ int sums[1024];
    const int tid = threadIdx.x;
    const int PER = 20;
    int base = tid * PER;

    int local = 0;
#pragma unroll
    for (int j = 0; j < PER; j++) {
        int b = base + j;
        if (b < T_NODES) local += g_cnt[b];
    }
    sums[tid] = local;
    __syncthreads();

    for (int d = 1; d < 1024; d <<= 1) {
        int v = sums[tid];
        int add = (tid >= d) ? sums[tid - d] : 0;
        __syncthreads();
        sums[tid] = v + add;
        __syncthreads();
    }

    int run = (tid > 0) ? sums[tid - 1] : 0;
#pragma unroll
    for (int j = 0; j < PER; j++) {
        int b = base + j;
        if (b < T_NODES) {
            g_off[b] = run;
            g_cur[b] = run;
            run += g_cnt[b];
        }
    }
}

// Bucket fill, 4-way unrolled so 4 independent atomics are in flight
__global__ void __launch_bounds__(256)
fill_kernel(const int* __restrict__ src, const int* __restrict__ dst) {
    int tid = blockIdx.x * blockDim.x + threadIdx.x;
    int nthreads = gridDim.x * blockDim.x;
    // each thread owns 4 strided positions per iteration
    for (int base = tid * 4; base < E_EDGES; base += nthreads * 4) {
        int d0 = -1, d1 = -1, d2 = -1, d3 = -1;
        int s0 = 0, s1 = 0, s2 = 0, s3 = 0;
        if (base + 0 < E_EDGES) { d0 = dst[base + 0]; s0 = src[base + 0]; }
        if (base + 1 < E_EDGES) { d1 = dst[base + 1]; s1 = src[base + 1]; }
        if (base + 2 < E_EDGES) { d2 = dst[base + 2]; s2 = src[base + 2]; }
        if (base + 3 < E_EDGES) { d3 = dst[base + 3]; s3 = src[base + 3]; }
        int p0 = (d0 >= 0) ? atomicAdd(&g_cur[d0], 1) : 0;
        int p1 = (d1 >= 0) ? atomicAdd(&g_cur[d1], 1) : 0;
        int p2 = (d2 >= 0) ? atomicAdd(&g_cur[d2], 1) : 0;
        int p3 = (d3 >= 0) ? atomicAdd(&g_cur[d3], 1) : 0;
        if (d0 >= 0) g_bucket[p0] = s0;
        if (d1 >= 0) g_bucket[p1] = s1;
        if (d2 >= 0) g_bucket[p2] = s2;
        if (d3 >= 0) g_bucket[p3] = s3;
    }
}

// ---------------------------------------------------------------------------
// 64 threads per target; each thread owns one float4 of the 256-dim row.
// g_aggr[t] = (1/max(cnt,1)) * sum_{e in t} source_feat[src_e] * invnorm[src_e]
// ---------------------------------------------------------------------------
__global__ void __launch_bounds__(256)
aggregate256_kernel(const float* __restrict__ sf) {
    int gid  = blockIdx.x * blockDim.x + threadIdx.x;
    int grp  = gid >> 6;        // target id
    int c    = gid & 63;        // float4 column 0..63
    if (grp >= T_NODES) return;

    int beg = g_off[grp];
    int n   = g_cnt[grp];
    const float4* sf4 = (const float4*)sf;

    float4 a0 = make_float4(0.f, 0.f, 0.f, 0.f);
    float4 a1 = a0, a2 = a0, a3 = a0;

    int i = 0;
    for (; i + 4 <= n; i += 4) {
        int s0 = g_bucket[beg + i + 0];
        int s1 = g_bucket[beg + i + 1];
        int s2 = g_bucket[beg + i + 2];
        int s3 = g_bucket[beg + i + 3];
        float w0 = g_invnorm[s0];
        float w1 = g_invnorm[s1];
        float w2 = g_invnorm[s2];
        float w3 = g_invnorm[s3];
        float4 v0 = sf4[(size_t)s0 * 64 + c];
        float4 v1 = sf4[(size_t)s1 * 64 + c];
        float4 v2 = sf4[(size_t)s2 * 64 + c];
        float4 v3 = sf4[(size_t)s3 * 64 + c];
        a0.x += v0.x * w0; a0.y += v0.y * w0; a0.z += v0.z * w0; a0.w += v0.w * w0;
        a1.x += v1.x * w1; a1.y += v1.y * w1; a1.z += v1.z * w1; a1.w += v1.w * w1;
        a2.x += v2.x * w2; a2.y += v2.y * w2; a2.z += v2.z * w2; a2.w += v2.w * w2;
        a3.x += v3.x * w3; a3.y += v3.y * w3; a3.z += v3.z * w3; a3.w += v3.w * w3;
    }
    for (; i < n; i++) {
        int s = g_bucket[beg + i];
        float w = g_invnorm[s];
        float4 v = sf4[(size_t)s * 64 + c];
        a0.x += v.x * w; a0.y += v.y * w; a0.z += v.z * w; a0.w += v.w * w;
    }

    float inv = 1.0f / (float)(n > 1 ? n : 1);
    float4 r;
    r.x = (a0.x + a1.x + a2.x + a3.x) * inv;
    r.y = (a0.y + a1.y + a2.y + a3.y) * inv;
    r.z = (a0.z + a1.z + a2.z + a3.z) * inv;
    r.w = (a0.w + a1.w + a2.w + a3.w) * inv;
    ((float4*)g_aggr)[(size_t)grp * 64 + c] = r;
}

// ---------------------------------------------------------------------------
// fp32 GEMM, N fixed 128. BM=128, BN=128, BK=16, 256 threads, 8x8 tile.
// ---------------------------------------------------------------------------
__global__ void __launch_bounds__(256)
gemm128(const float* __restrict__ A, const float* __restrict__ B,
        float* __restrict__ C, int M, int K) {
    __shared__ float As[16][128];
    __shared__ float Bs[16][128];

    const int tid = threadIdx.x;
    const int tx  = tid & 15;
    const int ty  = tid >> 4;
    const int row0 = blockIdx.x * 128;

    float c[8][8];
#pragma unroll
    for (int i = 0; i < 8; i++)
#pragma unroll
        for (int j = 0; j < 8; j++) c[i][j] = 0.0f;

    for (int k0 = 0; k0 < K; k0 += 16) {
#pragma unroll
        for (int l = 0; l < 2; l++) {
            int idx = tid * 2 + l;
            int r   = idx >> 2;
            int kq  = (idx & 3) * 4;
            int grow = row0 + r;
            float4 v = make_float4(0.f, 0.f, 0.f, 0.f);
            if (grow < M)
                v = *(const float4*)(A + (size_t)grow * K + k0 + kq);
            As[kq + 0][r] = v.x;
            As[kq + 1][r] = v.y;
            As[kq + 2][r] = v.z;
            As[kq + 3][r] = v.w;
        }
#pragma unroll
        for (int l = 0; l < 2; l++) {
            int idx = tid * 2 + l;
            int kr  = idx >> 5;
            int nq  = (idx & 31) * 4;
            *(float4*)&Bs[kr][nq] = *(const float4*)(B + (size_t)(k0 + kr) * 128 + nq);
        }
        __syncthreads();

#pragma unroll
        for (int k = 0; k < 16; k++) {
            float a[8], b[8];
#pragma unroll
            for (int i = 0; i < 8; i++) a[i] = As[k][ty * 8 + i];
#pragma unroll
            for (int j = 0; j < 8; j++) b[j] = Bs[k][tx * 8 + j];
#pragma unroll
            for (int i = 0; i < 8; i++)
#pragma unroll
                for (int j = 0; j < 8; j++) c[i][j] += a[i] * b[j];
        }
        __syncthreads();
    }

#pragma unroll
    for (int i = 0; i < 8; i++) {
        int grow = row0 + ty * 8 + i;
        if (grow >= M) continue;
#pragma unroll
        for (int j = 0; j < 8; j += 4) {
            float4 v;
            v.x = c[i][j + 0];
            v.y = c[i][j + 1];
            v.z = c[i][j + 2];
            v.w = c[i][j + 3];
            *(float4*)(C + (size_t)grow * 128 + tx * 8 + j) = v;
        }
    }
}

// ---------------------------------------------------------------------------
extern "C" void kernel_launch(void* const* d_in, const int* in_sizes, int n_in,
                              void* d_out, int out_size) {
    const float* source_feat = (const float*)d_in[0];  // [N, 256]
    const int*   src_idx     = (const int*)d_in[1];    // [E]
    const int*   dst_idx     = (const int*)d_in[2];    // [E]
    // d_in[3] = range_list (unused)
    const float* x_norm      = (const float*)d_in[4];  // [N]
    const float* embed       = (const float*)d_in[5];  // [256, 128]
    const float* weight      = (const float*)d_in[6];  // [128, 128]
    float* out = (float*)d_out;                        // [T, 128]

    float* gaggr;
    float* gM;
    cudaGetSymbolAddress((void**)&gaggr, g_aggr);
    cudaGetSymbolAddress((void**)&gM,    g_M);

    // CSR build + invnorm
    prep_kernel<<<(S_NODES + 255) / 256, 256>>>(x_norm);
    histogram_kernel<<<1024, 256>>>(dst_idx);
    scan_kernel<<<1, 1024>>>();
    fill_kernel<<<512, 256>>>(src_idx, dst_idx);

    // M = embed @ weight   [256,128]
    gemm128<<<2, 256>>>(embed, weight, gM, SRC_DIM, EMB_DIM);

    // aggr[t] = mean over edges of source_feat[src]/xnorm[src]  (256-dim)
    aggregate256_kernel<<<(T_NODES * 64 + 255) / 256, 256>>>(source_feat);

    // out = aggr @ M   [20000,256]@[256,128]
    gemm128<<<(T_NODES + 127) / 128, 256>>>(gaggr, gM, out, T_NODES, SRC_DIM);
}

// round 8
// speedup vs baseline: 2.8173x; 1.4050x over previous
#include <cuda_runtime.h>
#include <cstdint>

#define S_NODES 100000
#define T_NODES 20000
#define E_EDGES 1000000
#define SRC_DIM 256
#define EMB_DIM 128
#define TGT_DIM 128

// Scratch (__device__ globals; no allocations allowed)
__device__ float g_y[S_NODES * TGT_DIM];    // 51.2 MB  y = (sf/xnorm) @ (embed@weight)
__device__ float g_M[SRC_DIM * TGT_DIM];    // 128 KB   M = embed @ weight  [256][128]
__device__ int   g_cnt[T_NODES];
__device__ int   g_off[T_NODES];
__device__ int   g_cur[T_NODES];
__device__ int   g_bucket[E_EDGES];

// ===========================================================================
// CSR build
// ===========================================================================
__global__ void prep_kernel() {
    int i = blockIdx.x * blockDim.x + threadIdx.x;
    if (i < T_NODES) g_cnt[i] = 0;
}

__global__ void histogram_kernel(const int* __restrict__ dst) {
    int stride = gridDim.x * blockDim.x;
    for (int i = blockIdx.x * blockDim.x + threadIdx.x; i < E_EDGES; i += stride)
        atomicAdd(&g_cnt[dst[i]], 1);
}

__global__ void __launch_bounds__(1024)
scan_kernel() {
    __shared__ int sums[1024];
    const int tid = threadIdx.x;
    const int PER = 20;
    int base = tid * PER;
    int local = 0;
#pragma unroll
    for (int j = 0; j < PER; j++) {
        int b = base + j;
        if (b < T_NODES) local += g_cnt[b];
    }
    sums[tid] = local;
    __syncthreads();
    for (int d = 1; d < 1024; d <<= 1) {
        int v = sums[tid];
        int add = (tid >= d) ? sums[tid - d] : 0;
        __syncthreads();
        sums[tid] = v + add;
        __syncthreads();
    }
    int run = (tid > 0) ? sums[tid - 1] : 0;
#pragma unroll
    for (int j = 0; j < PER; j++) {
        int b = base + j;
        if (b < T_NODES) {
            g_off[b] = run;
            g_cur[b] = run;
            run += g_cnt[b];
        }
    }
}

__global__ void __launch_bounds__(256)
fill_kernel(const int* __restrict__ src, const int* __restrict__ dst) {
    int tid = blockIdx.x * blockDim.x + threadIdx.x;
    int nthreads = gridDim.x * blockDim.x;
    for (int base = tid * 4; base < E_EDGES; base += nthreads * 4) {
        int d0 = -1, d1 = -1, d2 = -1, d3 = -1;
        int s0 = 0, s1 = 0, s2 = 0, s3 = 0;
        if (base + 0 < E_EDGES) { d0 = dst[base + 0]; s0 = src[base + 0]; }
        if (base + 1 < E_EDGES) { d1 = dst[base + 1]; s1 = src[base + 1]; }
        if (base + 2 < E_EDGES) { d2 = dst[base + 2]; s2 = src[base + 2]; }
        if (base + 3 < E_EDGES) { d3 = dst[base + 3]; s3 = src[base + 3]; }
        int p0 = (d0 >= 0) ? atomicAdd(&g_cur[d0], 1) : 0;
        int p1 = (d1 >= 0) ? atomicAdd(&g_cur[d1], 1) : 0;
        int p2 = (d2 >= 0) ? atomicAdd(&g_cur[d2], 1) : 0;
        int p3 = (d3 >= 0) ? atomicAdd(&g_cur[d3], 1) : 0;
        if (d0 >= 0) g_bucket[p0] = s0;
        if (d1 >= 0) g_bucket[p1] = s1;
        if (d2 >= 0) g_bucket[p2] = s2;
        if (d3 >= 0) g_bucket[p3] = s3;
    }
}

// ===========================================================================
// M[k][n] = sum_e embed[k][e] * weight[e][n]   (row-major [256][128])
// ===========================================================================
__global__ void __launch_bounds__(128)
m_kernel(const float* __restrict__ embed, const float* __restrict__ weight) {
    __shared__ float er[EMB_DIM];
    int k = blockIdx.x;
    int n = threadIdx.x;
    if (n < EMB_DIM) er[n] = embed[k * EMB_DIM + n];
    __syncthreads();
    float acc = 0.f;
#pragma unroll 8
    for (int e = 0; e < EMB_DIM; e++)
        acc += er[e] * weight[e * TGT_DIM + n];
    g_M[k * TGT_DIM + n] = acc;
}

// ===========================================================================
// yGEMM via mma.sync tf32 (m16n8k8):
//   y[m][n] = (1/xnorm[m]) * sum_k sf[m][k] * M[k][n]
// BM=128, BN=128, BK=32. 256 threads = 8 warps, warp tile 32x64.
// ===========================================================================
__device__ __forceinline__ uint32_t cvt_tf32(float f) {
    uint32_t r;
    asm("cvt.rna.tf32.f32 %0, %1;" : "=r"(r) : "f"(f));
    return r;
}

__global__ void __launch_bounds__(256)
ygemm_kernel(const float* __restrict__ sf, const float* __restrict__ xnorm) {
    // pads chosen so fragment reads are conflict-free:
    // A read banks = (36*r + c) % 32 = (4r+c)%32, r=lane/4 in 0..7, c=lane%4 -> distinct
    // B read banks = (136*k + n) % 32 = (8k+n)%32, k=lane%4 in 0..3, n=lane/4 -> distinct
    __shared__ uint32_t As[128][36];
    __shared__ uint32_t Bs[32][136];

    const int tid  = threadIdx.x;
    const int wid  = tid >> 5;
    const int lane = tid & 31;
    const int warp_m = wid & 3;          // 0..3, 32 rows each
    const int warp_n = wid >> 2;         // 0..1, 64 cols each
    const int grp = lane >> 2;           // 0..7
    const int qd  = lane & 3;            // 0..3
    const int row0 = blockIdx.x * 128;

    float c[2][8][4];
#pragma unroll
    for (int mf = 0; mf < 2; mf++)
#pragma unroll
        for (int nf = 0; nf < 8; nf++)
#pragma unroll
            for (int j = 0; j < 4; j++) c[mf][nf][j] = 0.f;

    for (int kb = 0; kb < SRC_DIM; kb += 32) {
        // --- load A tile [128 x 32] ---
#pragma unroll
        for (int l = 0; l < 4; l++) {
            int idx = tid + 256 * l;          // 0..1023 float4 slots
            int r   = idx >> 3;               // 0..127
            int q   = idx & 7;                // 0..7 -> col q*4
            int grow = row0 + r;
            float4 v = make_float4(0.f, 0.f, 0.f, 0.f);
            if (grow < S_NODES)
                v = *(const float4*)(sf + (size_t)grow * SRC_DIM + kb + q * 4);
            As[r][q * 4 + 0] = cvt_tf32(v.x);
            As[r][q * 4 + 1] = cvt_tf32(v.y);
            As[r][q * 4 + 2] = cvt_tf32(v.z);
            As[r][q * 4 + 3] = cvt_tf32(v.w);
        }
        // --- load B tile [32 x 128] ---
#pragma unroll
        for (int l = 0; l < 4; l++) {
            int idx = tid + 256 * l;          // 0..1023
            int r   = idx >> 5;               // 0..31
            int q   = idx & 31;               // col q*4
            float4 v = *(const float4*)(g_M + (size_t)(kb + r) * TGT_DIM + q * 4);
            Bs[r][q * 4 + 0] = cvt_tf32(v.x);
            Bs[r][q * 4 + 1] = cvt_tf32(v.y);
            Bs[r][q * 4 + 2] = cvt_tf32(v.z);
            Bs[r][q * 4 + 3] = cvt_tf32(v.w);
        }
        __syncthreads();

#pragma unroll
        for (int k8 = 0; k8 < 32; k8 += 8) {
            uint32_t a[2][4];
#pragma unroll
            for (int mf = 0; mf < 2; mf++) {
                int rbase = warp_m * 32 + mf * 16;
                a[mf][0] = As[rbase + grp    ][k8 + qd    ];
                a[mf][1] = As[rbase + grp + 8][k8 + qd    ];
                a[mf][2] = As[rbase + grp    ][k8 + qd + 4];
                a[mf][3] = As[rbase + grp + 8][k8 + qd + 4];
            }
            uint32_t b[8][2];
#pragma unroll
            for (int nf = 0; nf < 8; nf++) {
                int nbase = warp_n * 64 + nf * 8 + grp;
                b[nf][0] = Bs[k8 + qd    ][nbase];
                b[nf][1] = Bs[k8 + qd + 4][nbase];
            }
#pragma unroll
            for (int mf = 0; mf < 2; mf++)
#pragma unroll
                for (int nf = 0; nf < 8; nf++) {
                    asm volatile(
                        "mma.sync.aligned.m16n8k8.row.col.f32.tf32.tf32.f32 "
                        "{%0,%1,%2,%3}, {%4,%5,%6,%7}, {%8,%9}, {%0,%1,%2,%3};"
                        : "+f"(c[mf][nf][0]), "+f"(c[mf][nf][1]),
                          "+f"(c[mf][nf][2]), "+f"(c[mf][nf][3])
                        : "r"(a[mf][0]), "r"(a[mf][1]), "r"(a[mf][2]), "r"(a[mf][3]),
                          "r"(b[nf][0]), "r"(b[nf][1]));
                }
        }
        __syncthreads();
    }

    // --- epilogue: scale by 1/xnorm[row], store float2 pairs ---
#pragma unroll
    for (int mf = 0; mf < 2; mf++) {
        int r_lo = row0 + warp_m * 32 + mf * 16 + grp;
        int r_hi = r_lo + 8;
        float inv_lo = (r_lo < S_NODES) ? (1.0f / xnorm[r_lo]) : 0.f;
        float inv_hi = (r_hi < S_NODES) ? (1.0f / xnorm[r_hi]) : 0.f;
#pragma unroll
        for (int nf = 0; nf < 8; nf++) {
            int col = warp_n * 64 + nf * 8 + qd * 2;
            if (r_lo < S_NODES) {
                float2 v;
                v.x = c[mf][nf][0] * inv_lo;
                v.y = c[mf][nf][1] * inv_lo;
                *(float2*)(g_y + (size_t)r_lo * TGT_DIM + col) = v;
            }
            if (r_hi < S_NODES) {
                float2 v;
                v.x = c[mf][nf][2] * inv_hi;
                v.y = c[mf][nf][3] * inv_hi;
                *(float2*)(g_y + (size_t)r_hi * TGT_DIM + col) = v;
            }
        }
    }
}

// ===========================================================================
// gather: out[t] = mean over edges of y[src]   (warp per target, 128-dim)
// ===========================================================================
__global__ void __launch_bounds__(256)
gather_kernel(float* __restrict__ out) {
    int warp = (blockIdx.x * blockDim.x + threadIdx.x) >> 5;
    int lane = threadIdx.x & 31;
    if (warp >= T_NODES) return;

    int beg = g_off[warp];
    int n   = g_cnt[warp];
    const float4* yb = (const float4*)g_y;

    float4 a0 = make_float4(0.f, 0.f, 0.f, 0.f);
    float4 a1 = a0, a2 = a0, a3 = a0;

    int i = 0;
    for (; i + 4 <= n; i += 4) {
        int s0 = g_bucket[beg + i + 0];
        int s1 = g_bucket[beg + i + 1];
        int s2 = g_bucket[beg + i + 2];
        int s3 = g_bucket[beg + i + 3];
        float4 v0 = yb[(size_t)s0 * 32 + lane];
        float4 v1 = yb[(size_t)s1 * 32 + lane];
        float4 v2 = yb[(size_t)s2 * 32 + lane];
        float4 v3 = yb[(size_t)s3 * 32 + lane];
        a0.x += v0.x; a0.y += v0.y; a0.z += v0.z; a0.w += v0.w;
        a1.x += v1.x; a1.y += v1.y; a1.z += v1.z; a1.w += v1.w;
        a2.x += v2.x; a2.y += v2.y; a2.z += v2.z; a2.w += v2.w;
        a3.x += v3.x; a3.y += v3.y; a3.z += v3.z; a3.w += v3.w;
    }
    for (; i < n; i++) {
        int s = g_bucket[beg + i];
        float4 v = yb[(size_t)s * 32 + lane];
        a0.x += v.x; a0.y += v.y; a0.z += v.z; a0.w += v.w;
    }

    float inv = 1.0f / (float)(n > 1 ? n : 1);
    float4 r;
    r.x = (a0.x + a1.x + a2.x + a3.x) * inv;
    r.y = (a0.y + a1.y + a2.y + a3.y) * inv;
    r.z = (a0.z + a1.z + a2.z + a3.z) * inv;
    r.w = (a0.w + a1.w + a2.w + a3.w) * inv;
    ((float4*)out)[(size_t)warp * 32 + lane] = r;
}

// ===========================================================================
extern "C" void kernel_launch(void* const* d_in, const int* in_sizes, int n_in,
                              void* d_out, int out_size) {
    const float* source_feat = (const float*)d_in[0];  // [N, 256]
    const int*   src_idx     = (const int*)d_in[1];    // [E]
    const int*   dst_idx     = (const int*)d_in[2];    // [E]
    // d_in[3] = range_list (unused)
    const float* x_norm      = (const float*)d_in[4];  // [N]
    const float* embed       = (const float*)d_in[5];  // [256, 128]
    const float* weight      = (const float*)d_in[6];  // [128, 128]
    float* out = (float*)d_out;                        // [T, 128]

    // CSR build
    prep_kernel<<<(T_NODES + 255) / 256, 256>>>();
    histogram_kernel<<<1024, 256>>>(dst_idx);
    scan_kernel<<<1, 1024>>>();
    fill_kernel<<<512, 256>>>(src_idx, dst_idx);

    // M = embed @ weight
    m_kernel<<<SRC_DIM, 128>>>(embed, weight);

    // y = (sf[:S]/xnorm) @ M   via mma.sync tf32
    ygemm_kernel<<<(S_NODES + 127) / 128, 256>>>(source_feat, x_norm);

    // out[t] = mean y[src]
    gather_kernel<<<(T_NODES * 32 + 255) / 256, 256>>>(out);
}

// round 10
// speedup vs baseline: 3.8498x; 1.3665x over previous
#include <cuda_runtime.h>
#include <cuda_fp16.h>
#include <cstdint>

#define S_NODES 100000
#define T_NODES 20000
#define E_EDGES 1000000
#define SRC_DIM 256
#define EMB_DIM 128
#define TGT_DIM 128

// Scratch (__device__ globals; no allocations allowed)
__device__ uint32_t g_y[S_NODES * (TGT_DIM / 2)];  // 25.6 MB  y rows as 64 half2
__device__ float    g_M[SRC_DIM * TGT_DIM];        // 128 KB   M = embed @ weight
__device__ int      g_cnt[T_NODES];
__device__ int      g_off[T_NODES];
__device__ int      g_cur[T_NODES];
__device__ int      g_bucket[E_EDGES];

// ===========================================================================
// CSR build
// ===========================================================================
__global__ void histogram_kernel(const int* __restrict__ dst) {
    int stride = gridDim.x * blockDim.x;
    for (int i = blockIdx.x * blockDim.x + threadIdx.x; i < E_EDGES; i += stride)
        atomicAdd(&g_cnt[dst[i]], 1);
}

__global__ void __launch_bounds__(1024)
scan_kernel() {
    __shared__ int sums[1024];
    const int tid = threadIdx.x;
    const int PER = 20;
    int base = tid * PER;
    int local = 0;
#pragma unroll
    for (int j = 0; j < PER; j++) {
        int b = base + j;
        if (b < T_NODES) local += g_cnt[b];
    }
    sums[tid] = local;
    __syncthreads();
    for (int d = 1; d < 1024; d <<= 1) {
        int v = sums[tid];
        int add = (tid >= d) ? sums[tid - d] : 0;
        __syncthreads();
        sums[tid] = v + add;
        __syncthreads();
    }
    int run = (tid > 0) ? sums[tid - 1] : 0;
#pragma unroll
    for (int j = 0; j < PER; j++) {
        int b = base + j;
        if (b < T_NODES) {
            g_off[b] = run;
            g_cur[b] = run;
            run += g_cnt[b];
        }
    }
}

__global__ void __launch_bounds__(256)
fill_kernel(const int* __restrict__ src, const int* __restrict__ dst) {
    int tid = blockIdx.x * blockDim.x + threadIdx.x;
    int nthreads = gridDim.x * blockDim.x;
    for (int base = tid * 4; base < E_EDGES; base += nthreads * 4) {
        int d0 = -1, d1 = -1, d2 = -1, d3 = -1;
        int s0 = 0, s1 = 0, s2 = 0, s3 = 0;
        if (base + 0 < E_EDGES) { d0 = dst[base + 0]; s0 = src[base + 0]; }
        if (base + 1 < E_EDGES) { d1 = dst[base + 1]; s1 = src[base + 1]; }
        if (base + 2 < E_EDGES) { d2 = dst[base + 2]; s2 = src[base + 2]; }
        if (base + 3 < E_EDGES) { d3 = dst[base + 3]; s3 = src[base + 3]; }
        int p0 = (d0 >= 0) ? atomicAdd(&g_cur[d0], 1) : 0;
        int p1 = (d1 >= 0) ? atomicAdd(&g_cur[d1], 1) : 0;
        int p2 = (d2 >= 0) ? atomicAdd(&g_cur[d2], 1) : 0;
        int p3 = (d3 >= 0) ? atomicAdd(&g_cur[d3], 1) : 0;
        if (d0 >= 0) g_bucket[p0] = s0;
        if (d1 >= 0) g_bucket[p1] = s1;
        if (d2 >= 0) g_bucket[p2] = s2;
        if (d3 >= 0) g_bucket[p3] = s3;
    }
}

// ===========================================================================
// M[k][n] = sum_e embed[k][e] * weight[e][n]
// ===========================================================================
__global__ void __launch_bounds__(128)
m_kernel(const float* __restrict__ embed, const float* __restrict__ weight) {
    __shared__ float er[EMB_DIM];
    int k = blockIdx.x;
    int n = threadIdx.x;
    if (n < EMB_DIM) er[n] = embed[k * EMB_DIM + n];
    __syncthreads();
    float acc = 0.f;
#pragma unroll 8
    for (int e = 0; e < EMB_DIM; e++)
        acc += er[e] * weight[e * TGT_DIM + n];
    g_M[k * TGT_DIM + n] = acc;
}

// ===========================================================================
// yGEMM via mma.sync tf32 (m16n8k8). Epilogue: scale by 1/xnorm, pack half2.
// BM=128, BN=128, BK=32, 256 threads, warp tile 32x64.
// ===========================================================================
__device__ __forceinline__ uint32_t cvt_tf32(float f) {
    uint32_t r;
    asm("cvt.rna.tf32.f32 %0, %1;" : "=r"(r) : "f"(f));
    return r;
}

__global__ void __launch_bounds__(256)
ygemm_kernel(const float* __restrict__ sf, const float* __restrict__ xnorm) {
    __shared__ uint32_t As[128][36];
    __shared__ uint32_t Bs[32][136];

    const int tid  = threadIdx.x;
    const int wid  = tid >> 5;
    const int lane = tid & 31;
    const int warp_m = wid & 3;
    const int warp_n = wid >> 2;
    const int grp = lane >> 2;
    const int qd  = lane & 3;
    const int row0 = blockIdx.x * 128;

    float c[2][8][4];
#pragma unroll
    for (int mf = 0; mf < 2; mf++)
#pragma unroll
        for (int nf = 0; nf < 8; nf++)
#pragma unroll
            for (int j = 0; j < 4; j++) c[mf][nf][j] = 0.f;

    for (int kb = 0; kb < SRC_DIM; kb += 32) {
#pragma unroll
        for (int l = 0; l < 4; l++) {
            int idx = tid + 256 * l;
            int r   = idx >> 3;
            int q   = idx & 7;
            int grow = row0 + r;
            float4 v = make_float4(0.f, 0.f, 0.f, 0.f);
            if (grow < S_NODES)
                v = *(const float4*)(sf + (size_t)grow * SRC_DIM + kb + q * 4);
            As[r][q * 4 + 0] = cvt_tf32(v.x);
            As[r][q * 4 + 1] = cvt_tf32(v.y);
            As[r][q * 4 + 2] = cvt_tf32(v.z);
            As[r][q * 4 + 3] = cvt_tf32(v.w);
        }
#pragma unroll
        for (int l = 0; l < 4; l++) {
            int idx = tid + 256 * l;
            int r   = idx >> 5;
            int q   = idx & 31;
            float4 v = *(const float4*)(g_M + (size_t)(kb + r) * TGT_DIM + q * 4);
            Bs[r][q * 4 + 0] = cvt_tf32(v.x);
            Bs[r][q * 4 + 1] = cvt_tf32(v.y);
            Bs[r][q * 4 + 2] = cvt_tf32(v.z);
            Bs[r][q * 4 + 3] = cvt_tf32(v.w);
        }
        __syncthreads();

#pragma unroll
        for (int k8 = 0; k8 < 32; k8 += 8) {
            uint32_t a[2][4];
#pragma unroll
            for (int mf = 0; mf < 2; mf++) {
                int rbase = warp_m * 32 + mf * 16;
                a[mf][0] = As[rbase + grp    ][k8 + qd    ];
                a[mf][1] = As[rbase + grp + 8][k8 + qd    ];
                a[mf][2] = As[rbase + grp    ][k8 + qd + 4];
                a[mf][3] = As[rbase + grp + 8][k8 + qd + 4];
            }
            uint32_t b[8][2];
#pragma unroll
            for (int nf = 0; nf < 8; nf++) {
                int nbase = warp_n * 64 + nf * 8 + grp;
                b[nf][0] = Bs[k8 + qd    ][nbase];
                b[nf][1] = Bs[k8 + qd + 4][nbase];
            }
#pragma unroll
            for (int mf = 0; mf < 2; mf++)
#pragma unroll
                for (int nf = 0; nf < 8; nf++) {
                    asm volatile(
                        "mma.sync.aligned.m16n8k8.row.col.f32.tf32.tf32.f32 "
                        "{%0,%1,%2,%3}, {%4,%5,%6,%7}, {%8,%9}, {%0,%1,%2,%3};"
                        : "+f"(c[mf][nf][0]), "+f"(c[mf][nf][1]),
                          "+f"(c[mf][nf][2]), "+f"(c[mf][nf][3])
                        : "r"(a[mf][0]), "r"(a[mf][1]), "r"(a[mf][2]), "r"(a[mf][3]),
                          "r"(b[nf][0]), "r"(b[nf][1]));
                }
        }
        __syncthreads();
    }

    // epilogue: scale by 1/xnorm, pack adjacent-n pair into half2 (one u32 store)
#pragma unroll
    for (int mf = 0; mf < 2; mf++) {
        int r_lo = row0 + warp_m * 32 + mf * 16 + grp;
        int r_hi = r_lo + 8;
        float inv_lo = (r_lo < S_NODES) ? (1.0f / xnorm[r_lo]) : 0.f;
        float inv_hi = (r_hi < S_NODES) ? (1.0f / xnorm[r_hi]) : 0.f;
#pragma unroll
        for (int nf = 0; nf < 8; nf++) {
            int col = warp_n * 64 + nf * 8 + qd * 2;   // even
            if (r_lo < S_NODES) {
                __half2 h = __floats2half2_rn(c[mf][nf][0] * inv_lo,
                                              c[mf][nf][1] * inv_lo);
                g_y[(size_t)r_lo * 64 + (col >> 1)] = *(uint32_t*)&h;
            }
            if (r_hi < S_NODES) {
                __half2 h = __floats2half2_rn(c[mf][nf][2] * inv_hi,
                                              c[mf][nf][3] * inv_hi);
                g_y[(size_t)r_hi * 64 + (col >> 1)] = *(uint32_t*)&h;
            }
        }
    }
}

// ===========================================================================
// gather: out[t] = mean over edges of y[src]  (warp/target; lane = 4 dims)
// y row = 64 half2 = 32 uint2; lane loads uint2 (4 halves), fp32 accumulate.
// ===========================================================================
__device__ __forceinline__ void acc_u2(float4& a, uint2 u) {
    float2 lo = __half22float2(*(__half2*)&u.x);
    float2 hi = __half22float2(*(__half2*)&u.y);
    a.x += lo.x; a.y += lo.y; a.z += hi.x; a.w += hi.y;
}

__global__ void __launch_bounds__(256)
gather_kernel(float* __restrict__ out) {
    int warp = (blockIdx.x * blockDim.x + threadIdx.x) >> 5;
    int lane = threadIdx.x & 31;
    if (warp >= T_NODES) return;

    int beg = g_off[warp];
    int n   = g_cnt[warp];
    const uint2* yb = (const uint2*)g_y;   // 32 uint2 per row

    float4 a0 = make_float4(0.f, 0.f, 0.f, 0.f);
    float4 a1 = a0, a2 = a0, a3 = a0;

    int i = 0;
    for (; i + 4 <= n; i += 4) {
        int s0 = g_bucket[beg + i + 0];
        int s1 = g_bucket[beg + i + 1];
        int s2 = g_bucket[beg + i + 2];
        int s3 = g_bucket[beg + i + 3];
        uint2 v0 = yb[(size_t)s0 * 32 + lane];
        uint2 v1 = yb[(size_t)s1 * 32 + lane];
        uint2 v2 = yb[(size_t)s2 * 32 + lane];
        uint2 v3 = yb[(size_t)s3 * 32 + lane];
        acc_u2(a0, v0); acc_u2(a1, v1); acc_u2(a2, v2); acc_u2(a3, v3);
    }
    for (; i < n; i++) {
        int s = g_bucket[beg + i];
        acc_u2(a0, yb[(size_t)s * 32 + lane]);
    }

    float inv = 1.0f / (float)(n > 1 ? n : 1);
    float4 r;
    r.x = (a0.x + a1.x + a2.x + a3.x) * inv;
    r.y = (a0.y + a1.y + a2.y + a3.y) * inv;
    r.z = (a0.z + a1.z + a2.z + a3.z) * inv;
    r.w = (a0.w + a1.w + a2.w + a3.w) * inv;
    ((float4*)out)[(size_t)warp * 32 + lane] = r;
}

// ===========================================================================
extern "C" void kernel_launch(void* const* d_in, const int* in_sizes, int n_in,
                              void* d_out, int out_size) {
    const float* source_feat = (const float*)d_in[0];  // [N, 256]
    const int*   src_idx     = (const int*)d_in[1];    // [E]
    const int*   dst_idx     = (const int*)d_in[2];    // [E]
    // d_in[3] = range_list (unused)
    const float* x_norm      = (const float*)d_in[4];  // [N]
    const float* embed       = (const float*)d_in[5];  // [256, 128]
    const float* weight      = (const float*)d_in[6];  // [128, 128]
    float* out = (float*)d_out;                        // [T, 128]

    static cudaStream_t s_side = nullptr;
    static cudaEvent_t ev_fork = nullptr, ev_join = nullptr;
    if (!s_side) {  // created on the uncaptured correctness call, reused under capture
        cudaStreamCreateWithFlags(&s_side, cudaStreamNonBlocking);
        cudaEventCreateWithFlags(&ev_fork, cudaEventDisableTiming);
        cudaEventCreateWithFlags(&ev_join, cudaEventDisableTiming);
    }

    int* gcnt;
    cudaGetSymbolAddress((void**)&gcnt, g_cnt);
    cudaMemsetAsync(gcnt, 0, T_NODES * sizeof(int), 0);

    // fork: GEMM chain on side stream, CSR chain on main stream
    cudaEventRecord(ev_fork, 0);
    cudaStreamWaitEvent(s_side, ev_fork, 0);

    m_kernel<<<SRC_DIM, 128, 0, s_side>>>(embed, weight);
    ygemm_kernel<<<(S_NODES + 127) / 128, 256, 0, s_side>>>(source_feat, x_norm);

    histogram_kernel<<<1024, 256>>>(dst_idx);
    scan_kernel<<<1, 1024>>>();
    fill_kernel<<<512, 256>>>(src_idx, dst_idx);

    // join
    cudaEventRecord(ev_join, s_side);
    cudaStreamWaitEvent(0, ev_join, 0);

    gather_kernel<<<(T_NODES * 32 + 255) / 256, 256>>>(out);
}

// round 11
// speedup vs baseline: 4.1630x; 1.0813x over previous
#include <cuda_runtime.h>
#include <cuda_fp16.h>
#include <cstdint>

#define S_NODES 100000
#define T_NODES 20000
#define E_EDGES 1000000
#define SRC_DIM 256
#define EMB_DIM 128
#define TGT_DIM 128

// Scratch (__device__ globals; no allocations allowed)
__device__ uint32_t g_y[S_NODES * (TGT_DIM / 2)];  // 25.6 MB  y rows as 64 half2
__device__ float    g_M[SRC_DIM * TGT_DIM];        // 128 KB   M = embed @ weight
__device__ int      g_cnt[T_NODES];
__device__ int      g_off[T_NODES];
__device__ int      g_rank[E_EDGES];               // 4 MB  per-edge rank within target
__device__ int      g_bucket[E_EDGES];

// ===========================================================================
// histogram + rank: rank[e] = position of edge e within its target bucket
// ===========================================================================
__global__ void __launch_bounds__(256)
hist_rank_kernel(const int* __restrict__ dst) {
    int stride = gridDim.x * blockDim.x;
    for (int i = blockIdx.x * blockDim.x + threadIdx.x; i < E_EDGES; i += stride)
        g_rank[i] = atomicAdd(&g_cnt[dst[i]], 1);
}

// ===========================================================================
// exclusive scan of g_cnt -> g_off  (single block, smem-staged, coalesced)
// ===========================================================================
__global__ void __launch_bounds__(1024)
scan_kernel() {
    extern __shared__ int s[];            // T_NODES ints (80 KB)
    __shared__ int wsum[32];
    const int tid  = threadIdx.x;
    const int lane = tid & 31;
    const int w    = tid >> 5;
    const int PER  = 20;                  // 1024*20 >= 20000

    // coalesced load
    for (int i = tid; i < T_NODES; i += 1024) s[i] = g_cnt[i];
    __syncthreads();

    // exclusive scan within this thread's chunk (in smem)
    int base = tid * PER;
    int sum = 0;
#pragma unroll
    for (int j = 0; j < PER; j++) {
        int b = base + j;
        if (b < T_NODES) {
            int v = s[b];
            s[b] = sum;
            sum += v;
        }
    }

    // warp-inclusive scan of per-thread sums
    int incl = sum;
#pragma unroll
    for (int d = 1; d < 32; d <<= 1) {
        int t = __shfl_up_sync(0xFFFFFFFF, incl, d);
        if (lane >= d) incl += t;
    }
    if (lane == 31) wsum[w] = incl;
    __syncthreads();
    if (w == 0) {
        int v = wsum[lane];
#pragma unroll
        for (int d = 1; d < 32; d <<= 1) {
            int t = __shfl_up_sync(0xFFFFFFFF, v, d);
            if (lane >= d) v += t;
        }
        wsum[lane] = v;
    }
    __syncthreads();

    int offset = (incl - sum) + (w > 0 ? wsum[w - 1] : 0);
#pragma unroll
    for (int j = 0; j < PER; j++) {
        int b = base + j;
        if (b < T_NODES) s[b] += offset;
    }
    __syncthreads();

    // coalesced write-out
    for (int i = tid; i < T_NODES; i += 1024) g_off[i] = s[i];
}

// ===========================================================================
// atomic-free bucket fill using precomputed ranks
// ===========================================================================
__global__ void __launch_bounds__(256)
fill_kernel(const int* __restrict__ src, const int* __restrict__ dst) {
    int stride = gridDim.x * blockDim.x;
    for (int i = blockIdx.x * blockDim.x + threadIdx.x; i < E_EDGES; i += stride) {
        int d = dst[i];
        g_bucket[g_off[d] + g_rank[i]] = src[i];
    }
}

// ===========================================================================
// M[k][n] = sum_e embed[k][e] * weight[e][n]
// ===========================================================================
__global__ void __launch_bounds__(128)
m_kernel(const float* __restrict__ embed, const float* __restrict__ weight) {
    __shared__ float er[EMB_DIM];
    int k = blockIdx.x;
    int n = threadIdx.x;
    if (n < EMB_DIM) er[n] = embed[k * EMB_DIM + n];
    __syncthreads();
    float acc = 0.f;
#pragma unroll 8
    for (int e = 0; e < EMB_DIM; e++)
        acc += er[e] * weight[e * TGT_DIM + n];
    g_M[k * TGT_DIM + n] = acc;
}

// ===========================================================================
// yGEMM via mma.sync tf32 (m16n8k8). Epilogue: scale by 1/xnorm, pack half2.
// BM=128, BN=128, BK=32, 256 threads, warp tile 32x64.
// ===========================================================================
__device__ __forceinline__ uint32_t cvt_tf32(float f) {
    uint32_t r;
    asm("cvt.rna.tf32.f32 %0, %1;" : "=r"(r) : "f"(f));
    return r;
}

__global__ void __launch_bounds__(256)
ygemm_kernel(const float* __restrict__ sf, const float* __restrict__ xnorm) {
    __shared__ uint32_t As[128][36];
    __shared__ uint32_t Bs[32][136];

    const int tid  = threadIdx.x;
    const int wid  = tid >> 5;
    const int lane = tid & 31;
    const int warp_m = wid & 3;
    const int warp_n = wid >> 2;
    const int grp = lane >> 2;
    const int qd  = lane & 3;
    const int row0 = blockIdx.x * 128;

    float c[2][8][4];
#pragma unroll
    for (int mf = 0; mf < 2; mf++)
#pragma unroll
        for (int nf = 0; nf < 8; nf++)
#pragma unroll
            for (int j = 0; j < 4; j++) c[mf][nf][j] = 0.f;

    for (int kb = 0; kb < SRC_DIM; kb += 32) {
#pragma unroll
        for (int l = 0; l < 4; l++) {
            int idx = tid + 256 * l;
            int r   = idx >> 3;
            int q   = idx & 7;
            int grow = row0 + r;
            float4 v = make_float4(0.f, 0.f, 0.f, 0.f);
            if (grow < S_NODES)
                v = *(const float4*)(sf + (size_t)grow * SRC_DIM + kb + q * 4);
            As[r][q * 4 + 0] = cvt_tf32(v.x);
            As[r][q * 4 + 1] = cvt_tf32(v.y);
            As[r][q * 4 + 2] = cvt_tf32(v.z);
            As[r][q * 4 + 3] = cvt_tf32(v.w);
        }
#pragma unroll
        for (int l = 0; l < 4; l++) {
            int idx = tid + 256 * l;
            int r   = idx >> 5;
            int q   = idx & 31;
            float4 v = *(const float4*)(g_M + (size_t)(kb + r) * TGT_DIM + q * 4);
            Bs[r][q * 4 + 0] = cvt_tf32(v.x);
            Bs[r][q * 4 + 1] = cvt_tf32(v.y);
            Bs[r][q * 4 + 2] = cvt_tf32(v.z);
            Bs[r][q * 4 + 3] = cvt_tf32(v.w);
        }
        __syncthreads();

#pragma unroll
        for (int k8 = 0; k8 < 32; k8 += 8) {
            uint32_t a[2][4];
#pragma unroll
            for (int mf = 0; mf < 2; mf++) {
                int rbase = warp_m * 32 + mf * 16;
                a[mf][0] = As[rbase + grp    ][k8 + qd    ];
                a[mf][1] = As[rbase + grp + 8][k8 + qd    ];
                a[mf][2] = As[rbase + grp    ][k8 + qd + 4];
                a[mf][3] = As[rbase + grp + 8][k8 + qd + 4];
            }
            uint32_t b[8][2];
#pragma unroll
            for (int nf = 0; nf < 8; nf++) {
                int nbase = warp_n * 64 + nf * 8 + grp;
                b[nf][0] = Bs[k8 + qd    ][nbase];
                b[nf][1] = Bs[k8 + qd + 4][nbase];
            }
#pragma unroll
            for (int mf = 0; mf < 2; mf++)
#pragma unroll
                for (int nf = 0; nf < 8; nf++) {
                    asm volatile(
                        "mma.sync.aligned.m16n8k8.row.col.f32.tf32.tf32.f32 "
                        "{%0,%1,%2,%3}, {%4,%5,%6,%7}, {%8,%9}, {%0,%1,%2,%3};"
                        : "+f"(c[mf][nf][0]), "+f"(c[mf][nf][1]),
                          "+f"(c[mf][nf][2]), "+f"(c[mf][nf][3])
                        : "r"(a[mf][0]), "r"(a[mf][1]), "r"(a[mf][2]), "r"(a[mf][3]),
                          "r"(b[nf][0]), "r"(b[nf][1]));
                }
        }
        __syncthreads();
    }

    // epilogue: scale by 1/xnorm, pack adjacent-n pair into half2
#pragma unroll
    for (int mf = 0; mf < 2; mf++) {
        int r_lo = row0 + warp_m * 32 + mf * 16 + grp;
        int r_hi = r_lo + 8;
        float inv_lo = (r_lo < S_NODES) ? (1.0f / xnorm[r_lo]) : 0.f;
        float inv_hi = (r_hi < S_NODES) ? (1.0f / xnorm[r_hi]) : 0.f;
#pragma unroll
        for (int nf = 0; nf < 8; nf++) {
            int col = warp_n * 64 + nf * 8 + qd * 2;
            if (r_lo < S_NODES) {
                __half2 h = __floats2half2_rn(c[mf][nf][0] * inv_lo,
                                              c[mf][nf][1] * inv_lo);
                g_y[(size_t)r_lo * 64 + (col >> 1)] = *(uint32_t*)&h;
            }
            if (r_hi < S_NODES) {
                __half2 h = __floats2half2_rn(c[mf][nf][2] * inv_hi,
                                              c[mf][nf][3] * inv_hi);
                g_y[(size_t)r_hi * 64 + (col >> 1)] = *(uint32_t*)&h;
            }
        }
    }
}

// ===========================================================================
// gather: out[t] = mean over edges of y[src]  (warp/target; lane = 4 dims)
// ===========================================================================
__device__ __forceinline__ void acc_u2(float4& a, uint2 u) {
    float2 lo = __half22float2(*(__half2*)&u.x);
    float2 hi = __half22float2(*(__half2*)&u.y);
    a.x += lo.x; a.y += lo.y; a.z += hi.x; a.w += hi.y;
}

__global__ void __launch_bounds__(256)
gather_kernel(float* __restrict__ out) {
    int warp = (blockIdx.x * blockDim.x + threadIdx.x) >> 5;
    int lane = threadIdx.x & 31;
    if (warp >= T_NODES) return;

    int beg = g_off[warp];
    int n   = g_cnt[warp];
    const uint2* yb = (const uint2*)g_y;

    float4 a0 = make_float4(0.f, 0.f, 0.f, 0.f);
    float4 a1 = a0, a2 = a0, a3 = a0;

    int i = 0;
    for (; i + 4 <= n; i += 4) {
        int s0 = g_bucket[beg + i + 0];
        int s1 = g_bucket[beg + i + 1];
        int s2 = g_bucket[beg + i + 2];
        int s3 = g_bucket[beg + i + 3];
        uint2 v0 = yb[(size_t)s0 * 32 + lane];
        uint2 v1 = yb[(size_t)s1 * 32 + lane];
        uint2 v2 = yb[(size_t)s2 * 32 + lane];
        uint2 v3 = yb[(size_t)s3 * 32 + lane];
        acc_u2(a0, v0); acc_u2(a1, v1); acc_u2(a2, v2); acc_u2(a3, v3);
    }
    for (; i < n; i++) {
        int s = g_bucket[beg + i];
        acc_u2(a0, yb[(size_t)s * 32 + lane]);
    }

    float inv = 1.0f / (float)(n > 1 ? n : 1);
    float4 r;
    r.x = (a0.x + a1.x + a2.x + a3.x) * inv;
    r.y = (a0.y + a1.y + a2.y + a3.y) * inv;
    r.z = (a0.z + a1.z + a2.z + a3.z) * inv;
    r.w = (a0.w + a1.w + a2.w + a3.w) * inv;
    ((float4*)out)[(size_t)warp * 32 + lane] = r;
}

// ===========================================================================
extern "C" void kernel_launch(void* const* d_in, const int* in_sizes, int n_in,
                              void* d_out, int out_size) {
    const float* source_feat = (const float*)d_in[0];  // [N, 256]
    const int*   src_idx     = (const int*)d_in[1];    // [E]
    const int*   dst_idx     = (const int*)d_in[2];    // [E]
    // d_in[3] = range_list (unused)
    const float* x_norm      = (const float*)d_in[4];  // [N]
    const float* embed       = (const float*)d_in[5];  // [256, 128]
    const float* weight      = (const float*)d_in[6];  // [128, 128]
    float* out = (float*)d_out;                        // [T, 128]

    static cudaStream_t s_side = nullptr;
    static cudaEvent_t ev_fork = nullptr, ev_join = nullptr;
    if (!s_side) {  // created on the uncaptured correctness call, reused under capture
        cudaStreamCreateWithFlags(&s_side, cudaStreamNonBlocking);
        cudaEventCreateWithFlags(&ev_fork, cudaEventDisableTiming);
        cudaEventCreateWithFlags(&ev_join, cudaEventDisableTiming);
        cudaFuncSetAttribute(scan_kernel,
                             cudaFuncAttributeMaxDynamicSharedMemorySize,
                             T_NODES * (int)sizeof(int));
    }

    int* gcnt;
    cudaGetSymbolAddress((void**)&gcnt, g_cnt);
    cudaMemsetAsync(gcnt, 0, T_NODES * sizeof(int), 0);

    // fork: GEMM chain on side stream, CSR chain on main stream
    cudaEventRecord(ev_fork, 0);
    cudaStreamWaitEvent(s_side, ev_fork, 0);

    m_kernel<<<SRC_DIM, 128, 0, s_side>>>(embed, weight);
    ygemm_kernel<<<(S_NODES + 127) / 128, 256, 0, s_side>>>(source_feat, x_norm);

    hist_rank_kernel<<<1024, 256>>>(dst_idx);
    scan_kernel<<<1, 1024, T_NODES * sizeof(int)>>>();
    fill_kernel<<<1024, 256>>>(src_idx, dst_idx);

    // join
    cudaEventRecord(ev_join, s_side);
    cudaStreamWaitEvent(0, ev_join, 0);

    gather_kernel<<<(T_NODES * 32 + 255) / 256, 256>>>(out);
}

// round 12
// speedup vs baseline: 4.1735x; 1.0025x over previous
#include <cuda_runtime.h>
#include <cuda_fp16.h>
#include <cstdint>

#define S_NODES 100000
#define T_NODES 20000
#define E_EDGES 1000000
#define SRC_DIM 256
#define EMB_DIM 128
#define TGT_DIM 128

// Scratch (__device__ globals; no allocations allowed)
__device__ uint32_t g_y[S_NODES * (TGT_DIM / 2)];  // 25.6 MB  y rows as 64 half2
__device__ float    g_M[SRC_DIM * TGT_DIM];        // 128 KB   M = embed @ weight
__device__ int      g_cnt[T_NODES];
__device__ int      g_off[T_NODES];
__device__ int      g_rank[E_EDGES];               // 4 MB  per-edge rank within target
__device__ int      g_bucket[E_EDGES];

// ===========================================================================
// histogram + rank, 4-way unrolled for atomic MLP
// ===========================================================================
__global__ void __launch_bounds__(256)
hist_rank_kernel(const int* __restrict__ dst) {
    int tid = blockIdx.x * blockDim.x + threadIdx.x;
    int nthreads = gridDim.x * blockDim.x;
    for (int base = tid * 4; base < E_EDGES; base += nthreads * 4) {
        int d0 = -1, d1 = -1, d2 = -1, d3 = -1;
        if (base + 0 < E_EDGES) d0 = dst[base + 0];
        if (base + 1 < E_EDGES) d1 = dst[base + 1];
        if (base + 2 < E_EDGES) d2 = dst[base + 2];
        if (base + 3 < E_EDGES) d3 = dst[base + 3];
        int r0 = (d0 >= 0) ? atomicAdd(&g_cnt[d0], 1) : 0;
        int r1 = (d1 >= 0) ? atomicAdd(&g_cnt[d1], 1) : 0;
        int r2 = (d2 >= 0) ? atomicAdd(&g_cnt[d2], 1) : 0;
        int r3 = (d3 >= 0) ? atomicAdd(&g_cnt[d3], 1) : 0;
        if (d0 >= 0) g_rank[base + 0] = r0;
        if (d1 >= 0) g_rank[base + 1] = r1;
        if (d2 >= 0) g_rank[base + 2] = r2;
        if (d3 >= 0) g_rank[base + 3] = r3;
    }
}

// ===========================================================================
// exclusive scan of g_cnt -> g_off
// single block; smem padded stride-21 per 20-chunk => conflict-free chunks
// ===========================================================================
__global__ void __launch_bounds__(1024)
scan_kernel() {
    extern __shared__ int s[];            // 21000 ints (84 KB), padded b -> b + b/20
    __shared__ int wsum[32];
    const int tid  = threadIdx.x;
    const int lane = tid & 31;
    const int w    = tid >> 5;
    const int PER  = 20;

    // coalesced load into padded layout
    for (int i = tid; i < T_NODES; i += 1024) s[i + i / 20] = g_cnt[i];
    __syncthreads();

    // exclusive scan within this thread's chunk; padded base = tid*21
    int p = tid * 21;
    int nvalid = T_NODES - tid * PER;     // may be <=0
    int sum = 0;
#pragma unroll
    for (int j = 0; j < PER; j++) {
        if (j < nvalid) {
            int v = s[p + j];
            s[p + j] = sum;
            sum += v;
        }
    }

    // warp-inclusive scan of per-thread sums
    int incl = sum;
#pragma unroll
    for (int d = 1; d < 32; d <<= 1) {
        int t = __shfl_up_sync(0xFFFFFFFF, incl, d);
        if (lane >= d) incl += t;
    }
    if (lane == 31) wsum[w] = incl;
    __syncthreads();
    if (w == 0) {
        int v = wsum[lane];
#pragma unroll
        for (int d = 1; d < 32; d <<= 1) {
            int t = __shfl_up_sync(0xFFFFFFFF, v, d);
            if (lane >= d) v += t;
        }
        wsum[lane] = v;
    }
    __syncthreads();

    int offset = (incl - sum) + (w > 0 ? wsum[w - 1] : 0);
#pragma unroll
    for (int j = 0; j < PER; j++) {
        if (j < nvalid) s[p + j] += offset;
    }
    __syncthreads();

    // coalesced write-out from padded layout
    for (int i = tid; i < T_NODES; i += 1024) g_off[i] = s[i + i / 20];
}

// ===========================================================================
// atomic-free bucket fill using precomputed ranks
// ===========================================================================
__global__ void __launch_bounds__(256)
fill_kernel(const int* __restrict__ src, const int* __restrict__ dst) {
    int stride = gridDim.x * blockDim.x;
    for (int i = blockIdx.x * blockDim.x + threadIdx.x; i < E_EDGES; i += stride) {
        int d = dst[i];
        g_bucket[g_off[d] + g_rank[i]] = src[i];
    }
}

// ===========================================================================
// M[k][n] = sum_e embed[k][e] * weight[e][n]
// ===========================================================================
__global__ void __launch_bounds__(128)
m_kernel(const float* __restrict__ embed, const float* __restrict__ weight) {
    __shared__ float er[EMB_DIM];
    int k = blockIdx.x;
    int n = threadIdx.x;
    if (n < EMB_DIM) er[n] = embed[k * EMB_DIM + n];
    __syncthreads();
    float acc = 0.f;
#pragma unroll 8
    for (int e = 0; e < EMB_DIM; e++)
        acc += er[e] * weight[e * TGT_DIM + n];
    g_M[k * TGT_DIM + n] = acc;
}

// ===========================================================================
// yGEMM via mma.sync tf32 (m16n8k8). Epilogue: scale by 1/xnorm, pack half2.
// BM=128, BN=128, BK=32, 256 threads, warp tile 32x64.
// ===========================================================================
__device__ __forceinline__ uint32_t cvt_tf32(float f) {
    uint32_t r;
    asm("cvt.rna.tf32.f32 %0, %1;" : "=r"(r) : "f"(f));
    return r;
}

__global__ void __launch_bounds__(256)
ygemm_kernel(const float* __restrict__ sf, const float* __restrict__ xnorm) {
    __shared__ uint32_t As[128][36];
    __shared__ uint32_t Bs[32][136];

    const int tid  = threadIdx.x;
    const int wid  = tid >> 5;
    const int lane = tid & 31;
    const int warp_m = wid & 3;
    const int warp_n = wid >> 2;
    const int grp = lane >> 2;
    const int qd  = lane & 3;
    const int row0 = blockIdx.x * 128;

    float c[2][8][4];
#pragma unroll
    for (int mf = 0; mf < 2; mf++)
#pragma unroll
        for (int nf = 0; nf < 8; nf++)
#pragma unroll
            for (int j = 0; j < 4; j++) c[mf][nf][j] = 0.f;

    for (int kb = 0; kb < SRC_DIM; kb += 32) {
#pragma unroll
        for (int l = 0; l < 4; l++) {
            int idx = tid + 256 * l;
            int r   = idx >> 3;
            int q   = idx & 7;
            int grow = row0 + r;
            float4 v = make_float4(0.f, 0.f, 0.f, 0.f);
            if (grow < S_NODES)
                v = *(const float4*)(sf + (size_t)grow * SRC_DIM + kb + q * 4);
            As[r][q * 4 + 0] = cvt_tf32(v.x);
            As[r][q * 4 + 1] = cvt_tf32(v.y);
            As[r][q * 4 + 2] = cvt_tf32(v.z);
            As[r][q * 4 + 3] = cvt_tf32(v.w);
        }
#pragma unroll
        for (int l = 0; l < 4; l++) {
            int idx = tid + 256 * l;
            int r   = idx >> 5;
            int q   = idx & 31;
            float4 v = *(const float4*)(g_M + (size_t)(kb + r) * TGT_DIM + q * 4);
            Bs[r][q * 4 + 0] = cvt_tf32(v.x);
            Bs[r][q * 4 + 1] = cvt_tf32(v.y);
            Bs[r][q * 4 + 2] = cvt_tf32(v.z);
            Bs[r][q * 4 + 3] = cvt_tf32(v.w);
        }
        __syncthreads();

#pragma unroll
        for (int k8 = 0; k8 < 32; k8 += 8) {
            uint32_t a[2][4];
#pragma unroll
            for (int mf = 0; mf < 2; mf++) {
                int rbase = warp_m * 32 + mf * 16;
                a[mf][0] = As[rbase + grp    ][k8 + qd    ];
                a[mf][1] = As[rbase + grp + 8][k8 + qd    ];
                a[mf][2] = As[rbase + grp    ][k8 + qd + 4];
                a[mf][3] = As[rbase + grp + 8][k8 + qd + 4];
            }
            uint32_t b[8][2];
#pragma unroll
            for (int nf = 0; nf < 8; nf++) {
                int nbase = warp_n * 64 + nf * 8 + grp;
                b[nf][0] = Bs[k8 + qd    ][nbase];
                b[nf][1] = Bs[k8 + qd + 4][nbase];
            }
#pragma unroll
            for (int mf = 0; mf < 2; mf++)
#pragma unroll
                for (int nf = 0; nf < 8; nf++) {
                    asm volatile(
                        "mma.sync.aligned.m16n8k8.row.col.f32.tf32.tf32.f32 "
                        "{%0,%1,%2,%3}, {%4,%5,%6,%7}, {%8,%9}, {%0,%1,%2,%3};"
                        : "+f"(c[mf][nf][0]), "+f"(c[mf][nf][1]),
                          "+f"(c[mf][nf][2]), "+f"(c[mf][nf][3])
                        : "r"(a[mf][0]), "r"(a[mf][1]), "r"(a[mf][2]), "r"(a[mf][3]),
                          "r"(b[nf][0]), "r"(b[nf][1]));
                }
        }
        __syncthreads();
    }

    // epilogue: scale by 1/xnorm, pack adjacent-n pair into half2
#pragma unroll
    for (int mf = 0; mf < 2; mf++) {
        int r_lo = row0 + warp_m * 32 + mf * 16 + grp;
        int r_hi = r_lo + 8;
        float inv_lo = (r_lo < S_NODES) ? (1.0f / xnorm[r_lo]) : 0.f;
        float inv_hi = (r_hi < S_NODES) ? (1.0f / xnorm[r_hi]) : 0.f;
#pragma unroll
        for (int nf = 0; nf < 8; nf++) {
            int col = warp_n * 64 + nf * 8 + qd * 2;
            if (r_lo < S_NODES) {
                __half2 h = __floats2half2_rn(c[mf][nf][0] * inv_lo,
                                              c[mf][nf][1] * inv_lo);
                g_y[(size_t)r_lo * 64 + (col >> 1)] = *(uint32_t*)&h;
            }
            if (r_hi < S_NODES) {
                __half2 h = __floats2half2_rn(c[mf][nf][2] * inv_hi,
                                              c[mf][nf][3] * inv_hi);
                g_y[(size_t)r_hi * 64 + (col >> 1)] = *(uint32_t*)&h;
            }
        }
    }
}

// ===========================================================================
// gather: out[t] = mean over edges of y[src]  (warp/target; lane = 4 dims)
// ===========================================================================
__device__ __forceinline__ void acc_u2(float4& a, uint2 u) {
    float2 lo = __half22float2(*(__half2*)&u.x);
    float2 hi = __half22float2(*(__half2*)&u.y);
    a.x += lo.x; a.y += lo.y; a.z += hi.x; a.w += hi.y;
}

__global__ void __launch_bounds__(256)
gather_kernel(float* __restrict__ out) {
    int warp = (blockIdx.x * blockDim.x + threadIdx.x) >> 5;
    int lane = threadIdx.x & 31;
    if (warp >= T_NODES) return;

    int beg = g_off[warp];
    int n   = g_cnt[warp];
    const uint2* yb = (const uint2*)g_y;

    float4 a0 = make_float4(0.f, 0.f, 0.f, 0.f);
    float4 a1 = a0, a2 = a0, a3 = a0;

    int i = 0;
    for (; i + 4 <= n; i += 4) {
        int s0 = g_bucket[beg + i + 0];
        int s1 = g_bucket[beg + i + 1];
        int s2 = g_bucket[beg + i + 2];
        int s3 = g_bucket[beg + i + 3];
        uint2 v0 = yb[(size_t)s0 * 32 + lane];
        uint2 v1 = yb[(size_t)s1 * 32 + lane];
        uint2 v2 = yb[(size_t)s2 * 32 + lane];
        uint2 v3 = yb[(size_t)s3 * 32 + lane];
        acc_u2(a0, v0); acc_u2(a1, v1); acc_u2(a2, v2); acc_u2(a3, v3);
    }
    for (; i < n; i++) {
        int s = g_bucket[beg + i];
        acc_u2(a0, yb[(size_t)s * 32 + lane]);
    }

    float inv = 1.0f / (float)(n > 1 ? n : 1);
    float4 r;
    r.x = (a0.x + a1.x + a2.x + a3.x) * inv;
    r.y = (a0.y + a1.y + a2.y + a3.y) * inv;
    r.z = (a0.z + a1.z + a2.z + a3.z) * inv;
    r.w = (a0.w + a1.w + a2.w + a3.w) * inv;
    ((float4*)out)[(size_t)warp * 32 + lane] = r;
}

// ===========================================================================
extern "C" void kernel_launch(void* const* d_in, const int* in_sizes, int n_in,
                              void* d_out, int out_size) {
    const float* source_feat = (const float*)d_in[0];  // [N, 256]
    const int*   src_idx     = (const int*)d_in[1];    // [E]
    const int*   dst_idx     = (const int*)d_in[2];    // [E]
    // d_in[3] = range_list (unused)
    const float* x_norm      = (const float*)d_in[4];  // [N]
    const float* embed       = (const float*)d_in[5];  // [256, 128]
    const float* weight      = (const float*)d_in[6];  // [128, 128]
    float* out = (float*)d_out;                        // [T, 128]

    const int SCAN_SMEM = (T_NODES + T_NODES / 20) * (int)sizeof(int);  // 84 KB

    static cudaStream_t s_side = nullptr;
    static cudaEvent_t ev_fork = nullptr, ev_join = nullptr;
    if (!s_side) {  // created on the uncaptured correctness call, reused under capture
        cudaStreamCreateWithFlags(&s_side, cudaStreamNonBlocking);
        cudaEventCreateWithFlags(&ev_fork, cudaEventDisableTiming);
        cudaEventCreateWithFlags(&ev_join, cudaEventDisableTiming);
        cudaFuncSetAttribute(scan_kernel,
                             cudaFuncAttributeMaxDynamicSharedMemorySize, SCAN_SMEM);
    }

    int* gcnt;
    cudaGetSymbolAddress((void**)&gcnt, g_cnt);
    cudaMemsetAsync(gcnt, 0, T_NODES * sizeof(int), 0);

    // fork: GEMM chain on side stream, CSR chain on main stream
    cudaEventRecord(ev_fork, 0);
    cudaStreamWaitEvent(s_side, ev_fork, 0);

    m_kernel<<<SRC_DIM, 128, 0, s_side>>>(embed, weight);
    ygemm_kernel<<<(S_NODES + 127) / 128, 256, 0, s_side>>>(source_feat, x_norm);

    hist_rank_kernel<<<1024, 256>>>(dst_idx);
    scan_kernel<<<1, 1024, SCAN_SMEM>>>();
    fill_kernel<<<1024, 256>>>(src_idx, dst_idx);

    // join
    cudaEventRecord(ev_join, s_side);
    cudaStreamWaitEvent(0, ev_join, 0);

    gather_kernel<<<(T_NODES * 32 + 255) / 256, 256>>>(out);
}